// round 2
// baseline (speedup 1.0000x reference)
#include <cuda_runtime.h>
#include <cuda_bf16.h>
#include <math.h>

#define BN 64
#define CN 64
#define LN 8192
#define CPB 16                       // CTAs per batch for the reduction
#define CHUNK (CN * LN / CPB)        // 32768 floats = 4 full rows of L
#define CHUNK4 (CHUNK / 4)           // 8192 float4 per CTA
#define EPSV 1.1920928955078125e-7f  // np.float32 eps

__device__ float2 g_partial[BN * CPB];  // (sum, sumsq) per CTA
__device__ float2 g_stats[BN];          // (mean, 1/(std+eps)) per batch

// ---------------------------------------------------------------------------
// Pass 1: masked partial reduction. One CTA handles 4 full L-rows of one batch.
// Loads are skipped entirely once l >= zero_pos[b] (prefix-only DRAM traffic).
// ---------------------------------------------------------------------------
__global__ __launch_bounds__(256) void reduce_kernel(
    const float* __restrict__ data, const int* __restrict__ zero_pos) {
    const int b = blockIdx.x / CPB;
    const int j = blockIdx.x % CPB;
    const int zp = zero_pos[b];

    const float4* base =
        reinterpret_cast<const float4*>(data + (size_t)b * CN * LN) + (size_t)j * CHUNK4;

    float s = 0.f, ss = 0.f;
    #pragma unroll 4
    for (int i = threadIdx.x; i < CHUNK4; i += 256) {
        const int l = (i * 4) & (LN - 1);  // chunk = whole rows, float4 stays in-row
        if (l < zp) {
            float4 v = base[i];
            if (l + 3 < zp) {
                s  += v.x + v.y + v.z + v.w;
                ss += v.x * v.x + v.y * v.y + v.z * v.z + v.w * v.w;
            } else {
                if (l + 0 < zp) { s += v.x; ss += v.x * v.x; }
                if (l + 1 < zp) { s += v.y; ss += v.y * v.y; }
                if (l + 2 < zp) { s += v.z; ss += v.z * v.z; }
                // l+3 >= zp here
            }
        }
    }

    // Block reduction: shared down to one value per warp, then warp shuffle.
    __shared__ float sh_s[8], sh_ss[8];
    const int lane = threadIdx.x & 31;
    const int warp = threadIdx.x >> 5;
    #pragma unroll
    for (int off = 16; off > 0; off >>= 1) {
        s  += __shfl_down_sync(0xffffffffu, s, off);
        ss += __shfl_down_sync(0xffffffffu, ss, off);
    }
    if (lane == 0) { sh_s[warp] = s; sh_ss[warp] = ss; }
    __syncthreads();
    if (warp == 0) {
        s  = (lane < 8) ? sh_s[lane]  : 0.f;
        ss = (lane < 8) ? sh_ss[lane] : 0.f;
        #pragma unroll
        for (int off = 4; off > 0; off >>= 1) {
            s  += __shfl_down_sync(0xffffffffu, s, off);
            ss += __shfl_down_sync(0xffffffffu, ss, off);
        }
        if (lane == 0)
            g_partial[b * CPB + j] = make_float2(s, ss);
    }
}

// ---------------------------------------------------------------------------
// Pass 2: combine partials -> mean, 1/(std+eps). Tiny (1 block, 64 threads).
// ---------------------------------------------------------------------------
__global__ void stats_kernel(const int* __restrict__ zero_pos) {
    const int b = threadIdx.x;  // blockDim.x == BN
    double s = 0.0, ss = 0.0;
    #pragma unroll
    for (int j = 0; j < CPB; j++) {
        float2 p = g_partial[b * CPB + j];
        s  += (double)p.x;
        ss += (double)p.y;
    }
    const double cnt  = (double)CN * (double)zero_pos[b];
    const double mean = s / cnt;
    const double var  = (ss - cnt * mean * mean) / (cnt - 1.0);
    const float  stdv = (float)sqrt(var > 0.0 ? var : 0.0);
    g_stats[b] = make_float2((float)mean, 1.0f / (stdv + EPSV));
}

// ---------------------------------------------------------------------------
// Pass 3: streaming normalize, one float4 per thread.
// ---------------------------------------------------------------------------
__global__ __launch_bounds__(256) void norm_kernel(
    const float* __restrict__ data, float* __restrict__ out) {
    const size_t i = (size_t)blockIdx.x * 256 + threadIdx.x;  // float4 index
    const int b = (int)(i >> 17);  // / (CN*LN/4) = 131072
    const float2 st = g_stats[b];
    float4 v = reinterpret_cast<const float4*>(data)[i];
    v.x = (v.x - st.x) * st.y;
    v.y = (v.y - st.x) * st.y;
    v.z = (v.z - st.x) * st.y;
    v.w = (v.w - st.x) * st.y;
    reinterpret_cast<float4*>(out)[i] = v;
}

// ---------------------------------------------------------------------------
// Pass 4: tail — idxes and zero_pos value-cast to float32 (tuple output).
// ---------------------------------------------------------------------------
__global__ __launch_bounds__(256) void tail_kernel(
    const int* __restrict__ idxes, const int* __restrict__ zero_pos,
    float* __restrict__ out, int tail_count) {
    const int i = blockIdx.x * 256 + threadIdx.x;
    if (i >= tail_count) return;
    const size_t base = (size_t)BN * CN * LN;
    if (i < BN * LN)
        out[base + i] = (float)idxes[i];
    else
        out[base + i] = (float)zero_pos[i - BN * LN];
}

extern "C" void kernel_launch(void* const* d_in, const int* in_sizes, int n_in,
                              void* d_out, int out_size) {
    const float* data     = (const float*)d_in[0];
    const int*   idxes    = (const int*)d_in[1];
    const int*   zero_pos = (const int*)d_in[2];
    float*       out      = (float*)d_out;

    reduce_kernel<<<BN * CPB, 256>>>(data, zero_pos);
    stats_kernel<<<1, BN>>>(zero_pos);

    const size_t n4 = (size_t)BN * CN * LN / 4;
    norm_kernel<<<(unsigned)(n4 / 256), 256>>>(data, out);

    const long long main_elems = (long long)BN * CN * LN;
    long long tail = (long long)out_size - main_elems;
    if (tail > 0) {
        long long want = (long long)BN * LN + BN;
        if (tail > want) tail = want;
        tail_kernel<<<(unsigned)((tail + 255) / 256), 256>>>(
            idxes, zero_pos, out, (int)tail);
    }
}